// round 11
// baseline (speedup 1.0000x reference)
#include <cuda_runtime.h>
#include <cstdint>
#include <math_constants.h>

// Problem constants
#define BB 64
#define SS 4096
#define DD 1024
#define SPLITS 32
#define CHUNK (SS / SPLITS)   // 128 rows per CTA
#define TILE 8                // rows per smem tile (== warps per CTA)
#define THREADS 256
#define NPART (BB * SPLITS)
#define ROW_BYTES (DD * 4)    // 4 KB

// Scratch (device globals — no allocation allowed)
__device__ float g_ctx[NPART * DD];
__device__ float g_m[NPART];
__device__ float g_l[NPART];
__device__ unsigned int g_cnt[BB];   // zero-init; self-resets each launch

__device__ __forceinline__ uint32_t smem_u32(const void* p) {
    return (uint32_t)__cvta_generic_to_shared(p);
}

__device__ __forceinline__ void mbar_init(uint32_t mbar, uint32_t count) {
    asm volatile("mbarrier.init.shared.b64 [%0], %1;" :: "r"(mbar), "r"(count) : "memory");
}
__device__ __forceinline__ void mbar_expect_tx(uint32_t mbar, uint32_t bytes) {
    asm volatile("mbarrier.arrive.expect_tx.shared.b64 _, [%0], %1;"
                 :: "r"(mbar), "r"(bytes) : "memory");
}
__device__ __forceinline__ void mbar_wait(uint32_t mbar, uint32_t parity) {
    asm volatile(
        "{\n\t"
        ".reg .pred P;\n\t"
        "WAIT_%=: \n\t"
        "mbarrier.try_wait.parity.shared.b64 P, [%0], %1;\n\t"
        "@!P bra WAIT_%=;\n\t"
        "}"
        :: "r"(mbar), "r"(parity) : "memory");
}
// 1D bulk TMA: gmem -> smem, completion via mbarrier complete_tx
__device__ __forceinline__ void tma_bulk_g2s(uint32_t dst_smem, const void* src,
                                             uint32_t bytes, uint32_t mbar) {
    asm volatile(
        "cp.async.bulk.shared::cluster.global.mbarrier::complete_tx::bytes "
        "[%0], [%1], %2, [%3];"
        :: "r"(dst_smem), "l"(src), "r"(bytes), "r"(mbar) : "memory");
}

// Single fused kernel: per-(batch, split) partial online-softmax attention
// pooling; the last-finishing CTA of each batch merges the partials and
// writes the final output row.
__global__ __launch_bounds__(THREADS, 3)
void attn_fused_kernel(const float* __restrict__ inp,
                       const int*   __restrict__ lens,
                       const float* __restrict__ w,
                       float*       __restrict__ out) {
    extern __shared__ float smem[];                 // 2 * TILE * DD floats = 64KB
    __shared__ float sc[TILE];                      // raw scores of tile rows
    __shared__ float pp[TILE];                      // exp(score - m_new)
    __shared__ float s_alpha;                       // rescale factor
    __shared__ __align__(8) uint64_t mbar_store[2]; // one mbarrier per stage
    __shared__ unsigned int s_ticket;
    __shared__ float mm[SPLITS], ll[SPLITS];

    const int sp  = blockIdx.x;
    const int b   = blockIdx.y;
    const int idx = b * SPLITS + sp;
    const int tid = threadIdx.x;
    const int lane = tid & 31;
    const int wid  = tid >> 5;

    const int len = lens[b];
    const int s0  = sp * CHUNK;
    const int s1  = min(s0 + CHUNK, len);

    // Empty split: nothing to contribute, not counted (merge triggers at n_active).
    if (s1 <= s0) return;

    const uint32_t mbar0 = smem_u32(&mbar_store[0]);
    const uint32_t mbar1 = smem_u32(&mbar_store[1]);
    if (tid == 0) {
        mbar_init(mbar0, 1);
        mbar_init(mbar1, 1);
    }
    __syncthreads();

    // Weight vector in registers: lane pattern matches the score-phase LDS.128 pattern.
    const float4* w4 = (const float4*)w;
    float4 wr[8];
#pragma unroll
    for (int j = 0; j < 8; j++) wr[j] = w4[lane + 32 * j];

    float* buf0 = smem;
    float* buf1 = smem + TILE * DD;
    const uint32_t sbuf0 = smem_u32(buf0);
    const uint32_t sbuf1 = smem_u32(buf1);

    const int nrows_total = s1 - s0;
    const int ntiles = (nrows_total + TILE - 1) / TILE;

    // Prologue: issue tile 0 (stage 0)
    if (tid == 0) {
        const int nr = min(TILE, nrows_total);
        const uint32_t bytes = nr * ROW_BYTES;
        mbar_expect_tx(mbar0, bytes);
        tma_bulk_g2s(sbuf0, inp + ((size_t)b * SS + s0) * DD, bytes, mbar0);
    }

    float m_run = -CUDART_INF_F;   // maintained by warp 0 only (uniform in-warp)
    float l_run = 0.0f;            // maintained by warp 0 only
    // ctx: thread owns columns 4*tid .. 4*tid+3
    float c0 = 0.f, c1 = 0.f, c2 = 0.f, c3 = 0.f;

    for (int t = 0; t < ntiles; t++) {
        // Issue next tile load into the other stage
        if (t + 1 < ntiles && tid == 0) {
            const int row0 = s0 + (t + 1) * TILE;
            const int nr = min(TILE, s1 - row0);
            const uint32_t bytes = nr * ROW_BYTES;
            const uint32_t mb = ((t + 1) & 1) ? mbar1 : mbar0;
            const uint32_t db = ((t + 1) & 1) ? sbuf1 : sbuf0;
            mbar_expect_tx(mb, bytes);
            tma_bulk_g2s(db, inp + ((size_t)b * SS + row0) * DD, bytes, mb);
        }

        // Wait for current tile
        const uint32_t mb_cur = (t & 1) ? mbar1 : mbar0;
        mbar_wait(mb_cur, (t >> 1) & 1);
        __syncthreads();

        const int nrows = min(TILE, s1 - (s0 + t * TILE));
        float* buf = (t & 1) ? buf1 : buf0;

        // --- Score phase: warp `wid` dots row `wid` against w (8 warps, 8 rows) ---
        if (wid < nrows) {
            const float4* row4 = (const float4*)(buf + wid * DD);
            float acc = 0.0f;
#pragma unroll
            for (int j = 0; j < 8; j++) {
                float4 v = row4[lane + 32 * j];
                acc += v.x * wr[j].x + v.y * wr[j].y + v.z * wr[j].z + v.w * wr[j].w;
            }
#pragma unroll
            for (int off = 16; off > 0; off >>= 1)
                acc += __shfl_xor_sync(0xFFFFFFFFu, acc, off);
            if (lane == 0) sc[wid] = acc;
        }
        __syncthreads();

        // --- Online softmax bookkeeping: warp 0 only ---
        if (wid == 0) {
            float s = (lane < nrows) ? sc[lane] : -CUDART_INF_F;
            float mt = s;
#pragma unroll
            for (int off = 16; off > 0; off >>= 1)
                mt = fmaxf(mt, __shfl_xor_sync(0xFFFFFFFFu, mt, off));
            const float m_new = fmaxf(m_run, mt);
            const float alpha = __expf(m_run - m_new);
            float p = (lane < nrows) ? __expf(s - m_new) : 0.0f;
            float psum = p;
#pragma unroll
            for (int off = 16; off > 0; off >>= 1)
                psum += __shfl_xor_sync(0xFFFFFFFFu, psum, off);
            l_run = l_run * alpha + psum;
            m_run = m_new;
            if (lane < TILE) pp[lane] = p;
            if (lane == 0) s_alpha = alpha;
        }
        __syncthreads();

        // --- Accumulate phase: each thread owns a float4 column group ---
        const float alpha = s_alpha;
        c0 *= alpha; c1 *= alpha; c2 *= alpha; c3 *= alpha;
        const float4* buf4 = (const float4*)buf;
#pragma unroll
        for (int r = 0; r < TILE; r++) {
            if (r >= nrows) break;
            const float p = pp[r];
            const float4 v = buf4[r * (DD / 4) + tid];
            c0 += p * v.x;
            c1 += p * v.y;
            c2 += p * v.z;
            c3 += p * v.w;
        }
        __syncthreads();   // buffer reuse guard (before next TMA overwrites)
    }

    // --- Write partial ---
    ((float4*)(g_ctx + (size_t)idx * DD))[tid] = make_float4(c0, c1, c2, c3);
    if (tid == 0) { g_m[idx] = m_run; g_l[idx] = l_run; }

    // --- Ticket: last active CTA of this batch merges ---
    __threadfence();          // make this CTA's partial visible device-wide
    __syncthreads();
    if (tid == 0) s_ticket = atomicAdd(&g_cnt[b], 1u);
    __syncthreads();

    const int n_active = (len + CHUNK - 1) / CHUNK;   // len >= 1
    if (s_ticket != (unsigned)(n_active - 1)) return;

    // We are the last CTA for batch b: all partials are visible (fence+atomic).
    __threadfence();          // acquire side

    if (tid < n_active) {
        mm[tid] = g_m[b * SPLITS + tid];
        ll[tid] = g_l[b * SPLITS + tid];
    }
    __syncthreads();

    float M = -CUDART_INF_F;
    for (int i = 0; i < n_active; i++) M = fmaxf(M, mm[i]);

    float L = 0.0f;
    for (int i = 0; i < n_active; i++) L += ll[i] * __expf(mm[i] - M);
    const float invL = 1.0f / L;

    float4 acc = make_float4(0.f, 0.f, 0.f, 0.f);
#pragma unroll 4
    for (int i = 0; i < n_active; i++) {
        const float wgi = __expf(mm[i] - M);
        const float4 v = ((const float4*)(g_ctx + (size_t)(b * SPLITS + i) * DD))[tid];
        acc.x += wgi * v.x;
        acc.y += wgi * v.y;
        acc.z += wgi * v.z;
        acc.w += wgi * v.w;
    }
    acc.x *= invL; acc.y *= invL; acc.z *= invL; acc.w *= invL;
    ((float4*)(out + (size_t)b * DD))[tid] = acc;

    // Reset counter for the next (graph-replayed) launch.
    if (tid == 0) g_cnt[b] = 0u;
}

extern "C" void kernel_launch(void* const* d_in, const int* in_sizes, int n_in,
                              void* d_out, int out_size) {
    const float* inp  = (const float*)d_in[0];
    const int*   lens = (const int*)d_in[1];
    const float* w    = (const float*)d_in[2];
    // d_in[3] = bias: softmax is shift-invariant -> ignored.
    float* out = (float*)d_out;

    const int smem_bytes = 2 * TILE * DD * sizeof(float);   // 64 KB
    cudaFuncSetAttribute(attn_fused_kernel,
                         cudaFuncAttributeMaxDynamicSharedMemorySize, smem_bytes);

    dim3 grid(SPLITS, BB);
    attn_fused_kernel<<<grid, THREADS, smem_bytes>>>(inp, lens, w, out);
}

// round 14
// speedup vs baseline: 1.0504x; 1.0504x over previous
#include <cuda_runtime.h>
#include <cstdint>
#include <math_constants.h>

// Problem constants
#define BB 64
#define SS 4096
#define DD 1024
#define SPLITS 32
#define CHUNK (SS / SPLITS)   // 128 rows per CTA
#define TILE 8                // rows per smem tile (== warps per CTA)
#define THREADS 256
#define NPART (BB * SPLITS)
#define ROW_BYTES (DD * 4)    // 4 KB

// Scratch (device globals — no allocation allowed)
__device__ float g_ctx[NPART * DD];
__device__ float g_m[NPART];
__device__ float g_l[NPART];

__device__ __forceinline__ uint32_t smem_u32(const void* p) {
    return (uint32_t)__cvta_generic_to_shared(p);
}

__device__ __forceinline__ void mbar_init(uint32_t mbar, uint32_t count) {
    asm volatile("mbarrier.init.shared.b64 [%0], %1;" :: "r"(mbar), "r"(count) : "memory");
}
__device__ __forceinline__ void mbar_expect_tx(uint32_t mbar, uint32_t bytes) {
    asm volatile("mbarrier.arrive.expect_tx.shared.b64 _, [%0], %1;"
                 :: "r"(mbar), "r"(bytes) : "memory");
}
__device__ __forceinline__ void mbar_wait(uint32_t mbar, uint32_t parity) {
    asm volatile(
        "{\n\t"
        ".reg .pred P;\n\t"
        "WAIT_%=: \n\t"
        "mbarrier.try_wait.parity.shared.b64 P, [%0], %1;\n\t"
        "@!P bra WAIT_%=;\n\t"
        "}"
        :: "r"(mbar), "r"(parity) : "memory");
}
// 1D bulk TMA: gmem -> smem, completion via mbarrier complete_tx
__device__ __forceinline__ void tma_bulk_g2s(uint32_t dst_smem, const void* src,
                                             uint32_t bytes, uint32_t mbar) {
    asm volatile(
        "cp.async.bulk.shared::cluster.global.mbarrier::complete_tx::bytes "
        "[%0], [%1], %2, [%3];"
        :: "r"(dst_smem), "l"(src), "r"(bytes), "r"(mbar) : "memory");
}

// Kernel 1: per-(batch, split) partial online-softmax attention pooling.
// Tile pipeline: 2 x (8 rows x 4KB) smem buffers, TMA bulk double buffered.
// 64KB dynamic smem -> 3 CTAs/SM. Empty splits exit without any writes.
__global__ __launch_bounds__(THREADS, 3)
void attn_partial_kernel(const float* __restrict__ inp,
                         const int*   __restrict__ lens,
                         const float* __restrict__ w) {
    extern __shared__ float smem[];                 // 2 * TILE * DD floats = 64KB
    __shared__ float sc[TILE];                      // raw scores of tile rows
    __shared__ float pp[TILE];                      // exp(score - m_new)
    __shared__ float s_alpha;                       // rescale factor
    __shared__ __align__(8) uint64_t mbar_store[2]; // one mbarrier per stage

    const int sp  = blockIdx.x;
    const int b   = blockIdx.y;
    const int idx = b * SPLITS + sp;
    const int tid = threadIdx.x;
    const int lane = tid & 31;
    const int wid  = tid >> 5;

    const int len = lens[b];
    const int s0  = sp * CHUNK;
    const int s1  = min(s0 + CHUNK, len);

    // Empty split: reduce kernel only reads active splits -> nothing to do.
    if (s1 <= s0) return;

    const uint32_t mbar0 = smem_u32(&mbar_store[0]);
    const uint32_t mbar1 = smem_u32(&mbar_store[1]);
    if (tid == 0) {
        mbar_init(mbar0, 1);
        mbar_init(mbar1, 1);
    }
    __syncthreads();

    // Weight vector in registers: lane pattern matches the score-phase LDS.128 pattern.
    const float4* w4 = (const float4*)w;
    float4 wr[8];
#pragma unroll
    for (int j = 0; j < 8; j++) wr[j] = w4[lane + 32 * j];

    float* buf0 = smem;
    float* buf1 = smem + TILE * DD;
    const uint32_t sbuf0 = smem_u32(buf0);
    const uint32_t sbuf1 = smem_u32(buf1);

    const int nrows_total = s1 - s0;
    const int ntiles = (nrows_total + TILE - 1) / TILE;

    // Prologue: issue tile 0 (stage 0)
    if (tid == 0) {
        const int nr = min(TILE, nrows_total);
        const uint32_t bytes = nr * ROW_BYTES;
        mbar_expect_tx(mbar0, bytes);
        tma_bulk_g2s(sbuf0, inp + ((size_t)b * SS + s0) * DD, bytes, mbar0);
    }

    float m_run = -CUDART_INF_F;   // maintained by warp 0 only (uniform in-warp)
    float l_run = 0.0f;            // maintained by warp 0 only
    // ctx: thread owns columns 4*tid .. 4*tid+3
    float c0 = 0.f, c1 = 0.f, c2 = 0.f, c3 = 0.f;

    for (int t = 0; t < ntiles; t++) {
        // Issue next tile load into the other stage
        if (t + 1 < ntiles && tid == 0) {
            const int row0 = s0 + (t + 1) * TILE;
            const int nr = min(TILE, s1 - row0);
            const uint32_t bytes = nr * ROW_BYTES;
            const uint32_t mb = ((t + 1) & 1) ? mbar1 : mbar0;
            const uint32_t db = ((t + 1) & 1) ? sbuf1 : sbuf0;
            mbar_expect_tx(mb, bytes);
            tma_bulk_g2s(db, inp + ((size_t)b * SS + row0) * DD, bytes, mb);
        }

        // Wait for current tile
        const uint32_t mb_cur = (t & 1) ? mbar1 : mbar0;
        mbar_wait(mb_cur, (t >> 1) & 1);
        __syncthreads();

        const int nrows = min(TILE, s1 - (s0 + t * TILE));
        float* buf = (t & 1) ? buf1 : buf0;

        // --- Score phase: warp `wid` dots row `wid` against w (8 warps, 8 rows) ---
        if (wid < nrows) {
            const float4* row4 = (const float4*)(buf + wid * DD);
            float acc = 0.0f;
#pragma unroll
            for (int j = 0; j < 8; j++) {
                float4 v = row4[lane + 32 * j];
                acc += v.x * wr[j].x + v.y * wr[j].y + v.z * wr[j].z + v.w * wr[j].w;
            }
#pragma unroll
            for (int off = 16; off > 0; off >>= 1)
                acc += __shfl_xor_sync(0xFFFFFFFFu, acc, off);
            if (lane == 0) sc[wid] = acc;
        }
        __syncthreads();

        // --- Online softmax bookkeeping: warp 0 only ---
        if (wid == 0) {
            float s = (lane < nrows) ? sc[lane] : -CUDART_INF_F;
            float mt = s;
#pragma unroll
            for (int off = 16; off > 0; off >>= 1)
                mt = fmaxf(mt, __shfl_xor_sync(0xFFFFFFFFu, mt, off));
            const float m_new = fmaxf(m_run, mt);
            const float alpha = __expf(m_run - m_new);
            float p = (lane < nrows) ? __expf(s - m_new) : 0.0f;
            float psum = p;
#pragma unroll
            for (int off = 16; off > 0; off >>= 1)
                psum += __shfl_xor_sync(0xFFFFFFFFu, psum, off);
            l_run = l_run * alpha + psum;
            m_run = m_new;
            if (lane < TILE) pp[lane] = p;
            if (lane == 0) s_alpha = alpha;
        }
        __syncthreads();

        // --- Accumulate phase: each thread owns a float4 column group ---
        const float alpha = s_alpha;
        c0 *= alpha; c1 *= alpha; c2 *= alpha; c3 *= alpha;
        const float4* buf4 = (const float4*)buf;
#pragma unroll
        for (int r = 0; r < TILE; r++) {
            if (r >= nrows) break;
            const float p = pp[r];
            const float4 v = buf4[r * (DD / 4) + tid];
            c0 += p * v.x;
            c1 += p * v.y;
            c2 += p * v.z;
            c3 += p * v.w;
        }
        __syncthreads();   // buffer reuse guard (before next TMA overwrites)
    }

    // Write partial
    ((float4*)(g_ctx + (size_t)idx * DD))[tid] = make_float4(c0, c1, c2, c3);
    if (tid == 0) { g_m[idx] = m_run; g_l[idx] = l_run; }
}

// Kernel 2: merge active partials per batch (split-softmax merge).
// grid (BB, 8) x 32 threads: each block owns 32 float4 columns of one batch.
// One warp: m/l stats via shuffle, then up to 32 independent LDG.128 per lane.
__global__ __launch_bounds__(32)
void attn_reduce_kernel(const int* __restrict__ lens, float* __restrict__ out) {
    const int b    = blockIdx.x;
    const int zb   = blockIdx.y;          // 0..7 column strip
    const int lane = threadIdx.x;         // 0..31

#if __CUDA_ARCH__ >= 900
    cudaGridDependencySynchronize();      // PDL: wait for partial kernel results
#endif

    const int len = lens[b];
    const int n_active = (len + CHUNK - 1) / CHUNK;   // 1..32

    // One load per lane, then shuffle-reduce the stats.
    float m_lane = (lane < n_active) ? g_m[b * SPLITS + lane] : -CUDART_INF_F;
    float l_lane = (lane < n_active) ? g_l[b * SPLITS + lane] : 0.0f;

    float M = m_lane;
#pragma unroll
    for (int off = 16; off > 0; off >>= 1)
        M = fmaxf(M, __shfl_xor_sync(0xFFFFFFFFu, M, off));

    const float wg_lane = (lane < n_active) ? __expf(m_lane - M) : 0.0f;
    float L = l_lane * wg_lane;
#pragma unroll
    for (int off = 16; off > 0; off >>= 1)
        L += __shfl_xor_sync(0xFFFFFFFFu, L, off);
    const float invL = 1.0f / L;

    const int c4 = zb * 32 + lane;        // float4 column index, 0..255

    float4 acc = make_float4(0.f, 0.f, 0.f, 0.f);
    for (int i = 0; i < n_active; i++) {
        const float wgi = __shfl_sync(0xFFFFFFFFu, wg_lane, i);
        const float4 v = ((const float4*)(g_ctx + (size_t)(b * SPLITS + i) * DD))[c4];
        acc.x += wgi * v.x;
        acc.y += wgi * v.y;
        acc.z += wgi * v.z;
        acc.w += wgi * v.w;
    }
    acc.x *= invL; acc.y *= invL; acc.z *= invL; acc.w *= invL;
    ((float4*)(out + (size_t)b * DD))[c4] = acc;
}

extern "C" void kernel_launch(void* const* d_in, const int* in_sizes, int n_in,
                              void* d_out, int out_size) {
    const float* inp  = (const float*)d_in[0];
    const int*   lens = (const int*)d_in[1];
    const float* w    = (const float*)d_in[2];
    // d_in[3] = bias: softmax is shift-invariant -> ignored.
    float* out = (float*)d_out;

    const int smem_bytes = 2 * TILE * DD * sizeof(float);   // 64 KB
    cudaFuncSetAttribute(attn_partial_kernel,
                         cudaFuncAttributeMaxDynamicSharedMemorySize, smem_bytes);

    dim3 grid1(SPLITS, BB);
    attn_partial_kernel<<<grid1, THREADS, smem_bytes>>>(inp, lens, w);

    // Reduce with PDL so its launch overlaps the partial kernel's tail.
    cudaLaunchConfig_t cfg = {};
    cfg.gridDim  = dim3(BB, 8);
    cfg.blockDim = dim3(32);
    cfg.dynamicSmemBytes = 0;
    cfg.stream = 0;
    cudaLaunchAttribute attrs[1];
    attrs[0].id = cudaLaunchAttributeProgrammaticStreamSerialization;
    attrs[0].val.programmaticStreamSerializationAllowed = 1;
    cfg.attrs = attrs;
    cfg.numAttrs = 1;
    cudaLaunchKernelEx(&cfg, attn_reduce_kernel, lens, out);
}